// round 13
// baseline (speedup 1.0000x reference)
#include <cuda_runtime.h>

#define NB 512
#define TT 1024
#define CC 64

typedef unsigned int u32;
typedef unsigned short u16;

__device__ __forceinline__ u32 pkbf2(float lo, float hi) {
    u32 r; asm("cvt.rn.bf16x2.f32 %0, %1, %2;" : "=r"(r) : "f"(hi), "f"(lo)); return r;
}
__device__ __forceinline__ u16 f2bf(float x) {
    u16 r; asm("cvt.rn.bf16.f32 %0, %1;" : "=h"(r) : "f"(x)); return r;
}
__device__ __forceinline__ float frcp(float x) {
    float r; asm("rcp.approx.f32 %0, %1;" : "=f"(r) : "f"(x)); return r;
}
__device__ __forceinline__ void mma16816(float& c0, float& c1, float& c2, float& c3,
                                         u32 a0, u32 a1, u32 a2, u32 a3,
                                         u32 b0, u32 b1) {
    asm("mma.sync.aligned.m16n8k16.row.col.f32.bf16.bf16.f32 "
        "{%0,%1,%2,%3}, {%4,%5,%6,%7}, {%8,%9}, {%0,%1,%2,%3};"
        : "+f"(c0), "+f"(c1), "+f"(c2), "+f"(c3)
        : "r"(a0), "r"(a1), "r"(a2), "r"(a3), "r"(b0), "r"(b1));
}

__global__ void __launch_bounds__(128, 1) crf_fwd_kernel(
    const float* __restrict__ logits,   // [NB, TT, CC]
    const float* __restrict__ trans,    // [CC, CC]  trans[i][j] = score j->i
    const float* __restrict__ init,     // [CC]
    const int*   __restrict__ lengths,  // [NB]
    const int*   __restrict__ tags,     // [NB, TT]
    float*       __restrict__ out)      // [NB]
{
    // one batch per CTA; full w vector (bf16) double-buffered + relay scalars
    __shared__ __align__(16) u16 wsh[2][CC];
    __shared__ float rn_sh[2];   // normalizer relay (parity slots)
    __shared__ float vb_sh[2];   // pre-rcp value for warp1's log accumulation
    __shared__ float gsum[4];    // per-warp row sums of final w
    __shared__ float gpart[4];   // per-warp gold-score partials

    const int tid  = threadIdx.x;
    const int wid  = tid >> 5;
    const int lane = tid & 31;
    const int g    = blockIdx.x;

    const float* lg = logits + (size_t)g * TT * CC;
    const int len = lengths[g];                     // uniform across CTA

    const int gid = lane >> 2;                      // 0..7
    const int tig = lane & 3;                       // 0..3
    const int r1  = 16 * wid + gid;                 // this lane's owned rows
    const int r2  = r1 + 8;                         // (warp0 lane0 -> row 0)

    // ---- E fragments for THIS warp's m-tile only: EA[kt][4] (16 regs)
    u32 EA[4][4];
    #pragma unroll
    for (int kt = 0; kt < 4; ++kt) {
        const int col = 16 * kt + 2 * tig;
        const float e00 = __expf(__ldg(trans + r1 * CC + col));
        const float e01 = __expf(__ldg(trans + r1 * CC + col + 1));
        const float e10 = __expf(__ldg(trans + r2 * CC + col));
        const float e11 = __expf(__ldg(trans + r2 * CC + col + 1));
        const float e08 = __expf(__ldg(trans + r1 * CC + col + 8));
        const float e09 = __expf(__ldg(trans + r1 * CC + col + 9));
        const float e18 = __expf(__ldg(trans + r2 * CC + col + 8));
        const float e19 = __expf(__ldg(trans + r2 * CC + col + 9));
        EA[kt][0] = pkbf2(e00, e01);
        EA[kt][1] = pkbf2(e10, e11);
        EA[kt][2] = pkbf2(e08, e09);
        EA[kt][3] = pkbf2(e18, e19);
    }

    // ---- w_0 = exp(init + logits[0])
    float w1 = __expf(__ldg(init + r1) + __ldg(lg + r1));
    float w2 = __expf(__ldg(init + r2) + __ldg(lg + r2));
    if (tig == 0) { wsh[0][r1] = f2bf(w1); wsh[0][r2] = f2bf(w2); }
    if (tid == 0) { rn_sh[0] = 1.0f; rn_sh[1] = 1.0f; vb_sh[0] = 1.0f; vb_sh[1] = 1.0f; }

    // ---- logit pipeline (distance-3 LDG cover, per lane: its two rows)
    float F1 = __expf(__ldg(lg + CC + r1));
    float F2 = __expf(__ldg(lg + CC + r2));
    const int c2i = (2 < len) ? 2 : (len - 1);
    const int c3i = (3 < len) ? 3 : (len - 1);
    float L1A = __ldg(lg + c2i * CC + r1), L1B = __ldg(lg + c2i * CC + r2);
    float L2A = __ldg(lg + c3i * CC + r1), L2B = __ldg(lg + c3i * CC + r2);

    float cacc = 0.0f;   // accumulated on warp 1 (all lanes, uniform)
    int buf = 0;
    __syncthreads();

    for (int t = 1; t < len; ++t) {
        // prefetch logits[t+3]
        const int tn = (t + 3 < len) ? (t + 3) : (len - 1);
        const float LnA = __ldg(lg + tn * CC + r1);
        const float LnB = __ldg(lg + tn * CC + r2);
        const float FnA = __expf(L1A);
        const float FnB = __expf(L1B);

        const float rp = rn_sh[(t - 1) & 1];        // normalizer for this step

        // ---- B fragments from full w vector (broadcast LDS.b32)
        const u32* wp = (const u32*)(&wsh[buf][0]);
        u32 b0[4], b1[4];
        #pragma unroll
        for (int kt = 0; kt < 4; ++kt) {
            b0[kt] = wp[8 * kt + tig];
            b1[kt] = wp[8 * kt + tig + 4];
        }

        // ---- this warp's 16 rows of D = E*w : 4 HMMA, depth-2 chains
        float ca0 = 0.0f, ca1 = 0.0f, ca2 = 0.0f, ca3 = 0.0f;
        float cb0 = 0.0f, cb1 = 0.0f, cb2 = 0.0f, cb3 = 0.0f;
        mma16816(ca0, ca1, ca2, ca3, EA[0][0], EA[0][1], EA[0][2], EA[0][3], b0[0], b1[0]);
        mma16816(cb0, cb1, cb2, cb3, EA[2][0], EA[2][1], EA[2][2], EA[2][3], b0[2], b1[2]);
        mma16816(ca0, ca1, ca2, ca3, EA[1][0], EA[1][1], EA[1][2], EA[1][3], b0[1], b1[1]);
        mma16816(cb0, cb1, cb2, cb3, EA[3][0], EA[3][1], EA[3][2], EA[3][3], b0[3], b1[3]);
        const float D1 = ca0 + cb0;                 // row r1 (all tig identical)
        const float D2 = ca2 + cb2;                 // row r2

        // ---- w_t = D * exp(logit_t) * rp
        w1 = D1 * F1 * rp;
        w2 = D2 * F2 * rp;
        if (tig == 0) { wsh[buf ^ 1][r1] = f2bf(w1); wsh[buf ^ 1][r2] = f2bf(w2); }

        // ---- warp 0: publish next normalizer (lane 0 owns state 0; no shfl)
        if (wid == 0) {
            const float vbl = fminf(fmaxf(w1, 1e-30f), 1e30f);
            const float rnl = frcp(vbl);
            if (lane == 0) { rn_sh[t & 1] = rnl; vb_sh[t & 1] = vbl; }
        }
        // ---- warp 1: fold the log of the factor applied THIS step (lagged slot)
        if (wid == 1 && t >= 2) {
            cacc += __logf(vb_sh[(t - 1) & 1]);
        }

        __syncthreads();                            // w + rn/vb visible for t+1
        buf ^= 1;

        F1 = FnA; F2 = FnB;
        L1A = L2A; L1B = L2B;
        L2A = LnA; L2B = LnB;
    }

    // ---- row sums of final w: reduce across gid (lanes sharing tig)
    float s = w1 + w2;
    s += __shfl_xor_sync(0xffffffffu, s, 4);
    s += __shfl_xor_sync(0xffffffffu, s, 8);
    s += __shfl_xor_sync(0xffffffffu, s, 16);
    if (lane == 0) gsum[wid] = s;

    // ---- gold path score: block-parallel over t
    const int* tg = tags + (size_t)g * TT;
    float gs = 0.0f;
    for (int t = 1 + tid; t < len; t += 128) {
        const int tc = __ldg(tg + t);
        const int tp = __ldg(tg + t - 1);
        gs += __ldg(trans + tc * CC + tp) + __ldg(lg + t * CC + tc);
    }
    #pragma unroll
    for (int o = 16; o; o >>= 1) gs += __shfl_xor_sync(0xffffffffu, gs, o);
    if (lane == 0) gpart[wid] = gs;
    __syncthreads();

    if (wid == 1 && lane == 0) {
        const float total = (gsum[0] + gsum[1]) + (gsum[2] + gsum[3]);
        const float logZ = cacc + __logf(total);
        const int tg0 = __ldg(tg);
        const float first = __ldg(init + tg0) + __ldg(lg + tg0);
        const float gold = first + (gpart[0] + gpart[1]) + (gpart[2] + gpart[3]);
        out[g] = logZ - gold;
    }
}

extern "C" void kernel_launch(void* const* d_in, const int* in_sizes, int n_in,
                              void* d_out, int out_size)
{
    const float* logits = (const float*)d_in[0];
    const float* trans  = (const float*)d_in[1];
    const float* init   = (const float*)d_in[2];
    const int*   lens   = (const int*)  d_in[3];
    const int*   tags   = (const int*)  d_in[4];
    float*       out    = (float*)d_out;

    crf_fwd_kernel<<<NB, 128>>>(logits, trans, init, lens, tags, out);
}